// round 2
// baseline (speedup 1.0000x reference)
#include <cuda_runtime.h>

#define BATCH 64
#define MM 512
#define NN 512
#define DH 64
#define NDIAG (MM + NN - 1)   /* 1023 */
#define GAMMA_F 0.1f
#define INVG 10.0f
#define BIGF 1e10f

// Diagonal-major distance matrix: Ddiag[b][(i+j)][i] = D[b][i][j] (0-based i,j)
__device__ float g_Ddiag[(size_t)BATCH * NDIAG * MM];
__device__ float g_perbatch[BATCH];

// ---------------------------------------------------------------------------
// Kernel 1: pairwise squared L2, written in diagonal-major layout.
// Grid: (NN/64, MM/64, BATCH), block 256 threads (16x16, 4x4 microtile).
// ---------------------------------------------------------------------------
__global__ __launch_bounds__(256) void pairwise_diag_kernel(
    const float* __restrict__ x, const float* __restrict__ y)
{
    __shared__ float xs[64][65];
    __shared__ float ys[64][65];
    __shared__ float Cs[64][66];   // stride 66 -> conflict-free diagonal reads

    int b  = blockIdx.z;
    int i0 = blockIdx.y * 64;
    int j0 = blockIdx.x * 64;
    int tid = threadIdx.x;

    const float* xb = x + (size_t)b * MM * DH;
    const float* yb = y + (size_t)b * NN * DH;

    // Load 64x64 tiles of x and y (coalesced: consecutive threads -> consecutive k)
    for (int e = tid; e < 64 * 64; e += 256) {
        int r = e >> 6, c = e & 63;
        xs[r][c] = xb[(i0 + r) * DH + c];
        ys[r][c] = yb[(j0 + r) * DH + c];
    }
    __syncthreads();

    int ty = tid >> 4, tx = tid & 15;
    float acc[4][4] = {};
    float xn[4] = {}, yn[4] = {};

    #pragma unroll 8
    for (int k = 0; k < DH; k++) {
        float a[4], bb[4];
        #pragma unroll
        for (int r = 0; r < 4; r++) a[r] = xs[ty * 4 + r][k];
        #pragma unroll
        for (int c = 0; c < 4; c++) bb[c] = ys[tx * 4 + c][k];
        #pragma unroll
        for (int r = 0; r < 4; r++) {
            xn[r] += a[r] * a[r];
            #pragma unroll
            for (int c = 0; c < 4; c++) acc[r][c] += a[r] * bb[c];
        }
        #pragma unroll
        for (int c = 0; c < 4; c++) yn[c] += bb[c] * bb[c];
    }

    #pragma unroll
    for (int r = 0; r < 4; r++)
        #pragma unroll
        for (int c = 0; c < 4; c++)
            Cs[ty * 4 + r][tx * 4 + c] =
                fmaxf(xn[r] + yn[c] - 2.0f * acc[r][c], 0.0f);
    __syncthreads();

    // Write tile anti-diagonals: for diag s, elements (li, s-li) go to
    // contiguous global addresses  (i0+j0+s)*MM + i0 + li  -> coalesced.
    // Shared read addr = li*66 + (s-li) = li*65 + s -> bank-conflict-free.
    float* out = g_Ddiag + (size_t)b * NDIAG * MM;
    int warp = tid >> 5, lane = tid & 31;
    for (int s = warp; s < 127; s += 8) {
        int lo = (s > 63) ? (s - 63) : 0;
        int hi = (s < 63) ? s : 63;
        for (int li = lo + lane; li <= hi; li += 32) {
            out[(size_t)(i0 + j0 + s) * MM + i0 + li] = Cs[li][s - li];
        }
    }
}

// ---------------------------------------------------------------------------
// Kernel 2: soft-DTW wavefront DP. One block per batch, 512 threads = one
// cell per thread per diagonal. Triple-buffered rows in shared memory,
// register prefetch of next diagonal's D to hide DRAM latency.
// ---------------------------------------------------------------------------
__global__ __launch_bounds__(512) void dtw_kernel()
{
    __shared__ float bufA[MM + 1];
    __shared__ float bufB[MM + 1];
    __shared__ float bufC[MM + 1];

    int b = blockIdx.x;
    int t = threadIdx.x;          // 0..511 ; i = t+1

    float* p2 = bufA;             // v_{d-2}
    float* p1 = bufB;             // v_{d-1}
    float* pd = bufC;             // v_d (write target; holds dead v_{d-3})

    // v0: [0, BIG, BIG, ...], v1: all BIG
    p2[t + 1] = BIGF;
    p1[t + 1] = BIGF;
    if (t == 0) { p2[0] = 0.0f; p1[0] = BIGF; }
    __syncthreads();

    const float* Db = g_Ddiag + (size_t)b * NDIAG * MM;
    float Dnext = Db[t];          // diagonal index 0  (d = 2)

    for (int d = 2; d <= MM + NN; d++) {
        float Dcur = Dnext;
        if (d < MM + NN)          // prefetch next diagonal early
            Dnext = Db[(size_t)(d - 1) * MM + t];

        int i = t + 1;
        int j = d - i;

        float r0 = p2[i - 1];
        float r1 = p1[i - 1];
        float r2 = p1[i];

        float m = fminf(r0, fminf(r1, r2));
        float s = __expf((m - r0) * INVG)
                + __expf((m - r1) * INVG)
                + __expf((m - r2) * INVG);
        float softmin = m - GAMMA_F * __logf(s);

        bool valid = (j >= 1) && (j <= NN);
        pd[i] = valid ? (Dcur + softmin) : BIGF;
        if (t == 0) pd[0] = BIGF;
        __syncthreads();

        float* tmp = p2; p2 = p1; p1 = pd; pd = tmp;
    }

    // After final rotation the last diagonal lives in p1.
    if (t == 0) g_perbatch[b] = p1[MM];
}

// ---------------------------------------------------------------------------
// Kernel 3: deterministic mean over batches.
// ---------------------------------------------------------------------------
__global__ void reduce_kernel(float* __restrict__ out)
{
    __shared__ float s[BATCH];
    s[threadIdx.x] = g_perbatch[threadIdx.x];
    __syncthreads();
    if (threadIdx.x == 0) {
        float acc = 0.0f;
        for (int i = 0; i < BATCH; i++) acc += s[i];
        out[0] = acc * (1.0f / BATCH);
    }
}

extern "C" void kernel_launch(void* const* d_in, const int* in_sizes, int n_in,
                              void* d_out, int out_size)
{
    const float* x = (const float*)d_in[0];
    const float* y = (const float*)d_in[1];
    float* out = (float*)d_out;

    dim3 g1(NN / 64, MM / 64, BATCH);
    pairwise_diag_kernel<<<g1, 256>>>(x, y);
    dtw_kernel<<<BATCH, 512>>>();
    reduce_kernel<<<1, BATCH>>>(out);
}